// round 15
// baseline (speedup 1.0000x reference)
#include <cuda_runtime.h>
#include <math.h>
#include <stdint.h>

#define Bn   4096
#define Lnn  4096
#define Hn   2048
#define Dn   128
#define D2n  256

// ---------------- scratch ----------------
__device__ float g_Hb[(size_t)2 * Bn * D2n];
__device__ float g_Zq[(size_t)Bn * Dn];
__device__ float g_Zr[(size_t)Lnn * Dn];
__device__ float g_mu[2 * Bn];
__device__ float g_rs[2 * Bn];
__device__ float g_W1T[128 * 256];

extern __shared__ char dynsm[];

// ================= helpers =================
__device__ __forceinline__ uint32_t f2tf32(float f) {
    uint32_t r;
    asm("cvt.rna.tf32.f32 %0, %1;" : "=r"(r) : "f"(f));
    return r;
}

__device__ __forceinline__ void mma_tf32(float* c, uint32_t a0, uint32_t a1, uint32_t a2, uint32_t a3,
                                         uint32_t b0, uint32_t b1) {
    asm volatile(
        "mma.sync.aligned.m16n8k8.row.col.f32.tf32.tf32.f32 "
        "{%0,%1,%2,%3}, {%4,%5,%6,%7}, {%8,%9}, {%0,%1,%2,%3};"
        : "+f"(c[0]), "+f"(c[1]), "+f"(c[2]), "+f"(c[3])
        : "r"(a0), "r"(a1), "r"(a2), "r"(a3), "r"(b0), "r"(b1));
}

__device__ __forceinline__ void cpa16(uint32_t dst, const void* src) {
    asm volatile("cp.async.cg.shared.global [%0], [%1], 16;" :: "r"(dst), "l"(src));
}
#define CP_COMMIT() asm volatile("cp.async.commit_group;" ::: "memory")
#define CP_WAIT1()  asm volatile("cp.async.wait_group 1;" ::: "memory")

// ---------------- row stats (z=0,1) + W1 transpose (z=2) in one launch ----------------
__global__ void rs_tw(const float* __restrict__ xq, const float* __restrict__ xr,
                      float* __restrict__ mu, float* __restrict__ rs,
                      const float* __restrict__ W1d, float* __restrict__ W1T) {
    int z = blockIdx.y;
    if (z == 2) {
        if (blockIdx.x >= 32) return;
        __shared__ float tsm[32][33];
        int bx = blockIdx.x & 7, by = blockIdx.x >> 3;
        int x = threadIdx.x & 31, y = threadIdx.x >> 5;  // 32 x 8
#pragma unroll
        for (int i = 0; i < 32; i += 8)
            tsm[y + i][x] = W1d[(by * 32 + y + i) * 256 + bx * 32 + x];
        __syncthreads();
#pragma unroll
        for (int i = 0; i < 32; i += 8)
            W1T[(bx * 32 + y + i) * 128 + by * 32 + x] = tsm[x][y + i];
        return;
    }
    const float* x = z ? xr : xq;
    int wid = threadIdx.x >> 5, lane = threadIdx.x & 31;
    int row = blockIdx.x * 8 + wid;
    const float4* xrow = (const float4*)(x + (size_t)row * Hn);
    float s = 0.f, sq = 0.f;
    for (int k = lane; k < Hn / 4; k += 32) {
        float4 v = xrow[k];
        s += v.x + v.y + v.z + v.w;
        sq += v.x * v.x + v.y * v.y + v.z * v.z + v.w * v.w;
    }
#pragma unroll
    for (int o = 16; o > 0; o >>= 1) {
        s += __shfl_xor_sync(~0u, s, o);
        sq += __shfl_xor_sync(~0u, sq, o);
    }
    if (lane == 0) {
        float m = s * (1.f / Hn);
        float var = sq * (1.f / Hn) - m * m;
        mu[z * Bn + row] = m;
        rs[z * Bn + row] = rsqrtf(var + 1e-5f);
    }
}

// ---------------- GEMM1 (tf32 mma) + fused LN + GELU, both paths via blockIdx.z ----------------
#define G1_LD 36
#define G1_AS (128 * G1_LD)
#define G1_BS (64 * G1_LD)
#define G1_SMEM ((2 * G1_AS + 2 * G1_BS) * 4)

__global__ void __launch_bounds__(256, 2) gemm1_both(
        const float* __restrict__ Aq, const float* __restrict__ Ar,
        const float* __restrict__ Wq, const float* __restrict__ Wr,
        const float* __restrict__ gq, const float* __restrict__ gr,
        const float* __restrict__ bq, const float* __restrict__ br,
        const float* __restrict__ biasq, const float* __restrict__ biasr,
        const float* __restrict__ mean, const float* __restrict__ rstd,
        float* __restrict__ Cb) {
    int z = blockIdx.z;
    const float* A = z ? Ar : Aq;
    const float* W = z ? Wr : Wq;
    const float* gamma = z ? gr : gq;
    const float* beta = z ? br : bq;
    const float* bias = z ? biasr : biasq;
    float* C = Cb + (size_t)z * Bn * D2n;
    const float* mub = mean + z * Bn;
    const float* rsb = rstd + z * Bn;

    uint32_t* sm = (uint32_t*)dynsm;
    uint32_t* Asm[2] = { sm, sm + G1_AS };
    uint32_t* Bsm[2] = { sm + 2 * G1_AS, sm + 2 * G1_AS + G1_BS };

    int tid = threadIdx.x;
    int wid = tid >> 5, lane = tid & 31;
    int wm = wid & 3, wn = wid >> 2;
    int g = lane >> 2, tig = lane & 3;
    int m0 = blockIdx.y * 128, n0 = blockIdx.x * 64;
    int q = tid >> 3, f4 = tid & 7;

    const float4* Arow[4];
    float mu[4], rsd[4];
#pragma unroll
    for (int j = 0; j < 4; j++) {
        int r = m0 + q + 32 * j;
        Arow[j] = (const float4*)(A + (size_t)r * Hn);
        mu[j] = mub[r];
        rsd[j] = rsb[r];
    }
    const float4* Brow[2];
#pragma unroll
    for (int j = 0; j < 2; j++) Brow[j] = (const float4*)(W + (size_t)(n0 + q + 32 * j) * Hn);
    const float4* g4p = (const float4*)gamma;
    const float4* b4p = (const float4*)beta;

    float acc[2][4][4] = {};
    float4 pA[4], pB[2], pG, pBt;

    const int NT = Hn / 32;  // 64

    pG = g4p[f4]; pBt = b4p[f4];
#pragma unroll
    for (int j = 0; j < 4; j++) pA[j] = Arow[j][f4];
#pragma unroll
    for (int j = 0; j < 2; j++) pB[j] = Brow[j][f4];
#pragma unroll
    for (int j = 0; j < 4; j++) {
        float x0 = (pA[j].x - mu[j]) * rsd[j] * pG.x + pBt.x;
        float x1 = (pA[j].y - mu[j]) * rsd[j] * pG.y + pBt.y;
        float x2 = (pA[j].z - mu[j]) * rsd[j] * pG.z + pBt.z;
        float x3 = (pA[j].w - mu[j]) * rsd[j] * pG.w + pBt.w;
        uint4 u = { f2tf32(x0), f2tf32(x1), f2tf32(x2), f2tf32(x3) };
        *(uint4*)&Asm[0][(q + 32 * j) * G1_LD + f4 * 4] = u;
    }
#pragma unroll
    for (int j = 0; j < 2; j++) {
        uint4 u = { f2tf32(pB[j].x), f2tf32(pB[j].y), f2tf32(pB[j].z), f2tf32(pB[j].w) };
        *(uint4*)&Bsm[0][(q + 32 * j) * G1_LD + f4 * 4] = u;
    }
    __syncthreads();

    for (int t = 0; t < NT; t++) {
        int cur = t & 1;
        if (t + 1 < NT) {
            pG = g4p[(t + 1) * 8 + f4]; pBt = b4p[(t + 1) * 8 + f4];
#pragma unroll
            for (int j = 0; j < 4; j++) pA[j] = Arow[j][(t + 1) * 8 + f4];
#pragma unroll
            for (int j = 0; j < 2; j++) pB[j] = Brow[j][(t + 1) * 8 + f4];
        }
        const uint32_t* Ab = Asm[cur];
        const uint32_t* Bb = Bsm[cur];
#pragma unroll
        for (int ks = 0; ks < 4; ks++) {
            int k = ks * 8;
            uint32_t bf[4][2];
#pragma unroll
            for (int nt = 0; nt < 4; nt++) {
                int nc = wn * 32 + nt * 8 + g;
                bf[nt][0] = Bb[nc * G1_LD + k + tig];
                bf[nt][1] = Bb[nc * G1_LD + k + tig + 4];
            }
#pragma unroll
            for (int mt = 0; mt < 2; mt++) {
                int mr = wm * 32 + mt * 16 + g;
                uint32_t a0 = Ab[mr * G1_LD + k + tig];
                uint32_t a1 = Ab[(mr + 8) * G1_LD + k + tig];
                uint32_t a2 = Ab[mr * G1_LD + k + tig + 4];
                uint32_t a3 = Ab[(mr + 8) * G1_LD + k + tig + 4];
#pragma unroll
                for (int nt = 0; nt < 4; nt++)
                    mma_tf32(acc[mt][nt], a0, a1, a2, a3, bf[nt][0], bf[nt][1]);
            }
        }
        if (t + 1 < NT) {
            int nxt = cur ^ 1;
#pragma unroll
            for (int j = 0; j < 4; j++) {
                float x0 = (pA[j].x - mu[j]) * rsd[j] * pG.x + pBt.x;
                float x1 = (pA[j].y - mu[j]) * rsd[j] * pG.y + pBt.y;
                float x2 = (pA[j].z - mu[j]) * rsd[j] * pG.z + pBt.z;
                float x3 = (pA[j].w - mu[j]) * rsd[j] * pG.w + pBt.w;
                uint4 u = { f2tf32(x0), f2tf32(x1), f2tf32(x2), f2tf32(x3) };
                *(uint4*)&Asm[nxt][(q + 32 * j) * G1_LD + f4 * 4] = u;
            }
#pragma unroll
            for (int j = 0; j < 2; j++) {
                uint4 u = { f2tf32(pB[j].x), f2tf32(pB[j].y), f2tf32(pB[j].z), f2tf32(pB[j].w) };
                *(uint4*)&Bsm[nxt][(q + 32 * j) * G1_LD + f4 * 4] = u;
            }
        }
        __syncthreads();
    }

#pragma unroll
    for (int mt = 0; mt < 2; mt++) {
#pragma unroll
        for (int nt = 0; nt < 4; nt++) {
            int n = n0 + wn * 32 + nt * 8 + 2 * tig;
            float bv0 = bias[n], bv1 = bias[n + 1];
#pragma unroll
            for (int rr = 0; rr < 2; rr++) {
                int m = m0 + wm * 32 + mt * 16 + g + rr * 8;
                float v0 = acc[mt][nt][rr * 2 + 0] + bv0;
                float v1 = acc[mt][nt][rr * 2 + 1] + bv1;
                v0 = 0.5f * v0 * (1.f + erff(v0 * 0.7071067811865475f));
                v1 = 0.5f * v1 * (1.f + erff(v1 * 0.7071067811865475f));
                float2 o = {v0, v1};
                *(float2*)(C + (size_t)m * D2n + n) = o;
            }
        }
    }
}

// ---------------- GEMM2 via tf32 mma + fused bias + l2norm. BM=64, grid (64, 2) ----------------
#define G2_LD 36
#define G2_AW (64 * G2_LD)
#define G2_BW (128 * G2_LD)
#define G2_SMEM ((2 * G2_AW + 2 * G2_BW) * 4)

__global__ void __launch_bounds__(256, 2) gemm2_mma(
        const float* __restrict__ Hb,
        const float* __restrict__ W2q, const float* __restrict__ W2r,
        const float* __restrict__ b2q, const float* __restrict__ b2r,
        float* __restrict__ Zq, float* __restrict__ Zr) {
    int z = blockIdx.y;
    const float* Hin = Hb + (size_t)z * Bn * D2n;
    const float* W2 = z ? W2r : W2q;
    const float* b2 = z ? b2r : b2q;
    float* Z = z ? Zr : Zq;

    uint32_t* sm = (uint32_t*)dynsm;
    uint32_t* Asm[2] = { sm, sm + G2_AW };
    uint32_t* Bsm[2] = { sm + 2 * G2_AW, sm + 2 * G2_AW + G2_BW };

    int tid = threadIdx.x;
    int wid = tid >> 5, lane = tid & 31;
    int wm = wid & 1, wn = wid >> 1;
    int g = lane >> 2, tig = lane & 3;
    int m0 = blockIdx.x * 64;
    int q8 = tid >> 3, f4 = tid & 7;

    const float4* Arow[2];
    const float4* Brow[4];
#pragma unroll
    for (int j = 0; j < 2; j++) Arow[j] = (const float4*)(Hin + (size_t)(m0 + q8 + 32 * j) * D2n);
#pragma unroll
    for (int j = 0; j < 4; j++) Brow[j] = (const float4*)(W2 + (size_t)(q8 + 32 * j) * D2n);

    float acc[2][4][4] = {};
    float4 pA[2], pB[4];
    const int NT = D2n / 32;  // 8

#pragma unroll
    for (int j = 0; j < 2; j++) pA[j] = Arow[j][f4];
#pragma unroll
    for (int j = 0; j < 4; j++) pB[j] = Brow[j][f4];
#pragma unroll
    for (int j = 0; j < 2; j++) {
        uint4 u = { f2tf32(pA[j].x), f2tf32(pA[j].y), f2tf32(pA[j].z), f2tf32(pA[j].w) };
        *(uint4*)&Asm[0][(q8 + 32 * j) * G2_LD + f4 * 4] = u;
    }
#pragma unroll
    for (int j = 0; j < 4; j++) {
        uint4 u = { f2tf32(pB[j].x), f2tf32(pB[j].y), f2tf32(pB[j].z), f2tf32(pB[j].w) };
        *(uint4*)&Bsm[0][(q8 + 32 * j) * G2_LD + f4 * 4] = u;
    }
    __syncthreads();

    for (int t = 0; t < NT; t++) {
        int cur = t & 1;
        if (t + 1 < NT) {
#pragma unroll
            for (int j = 0; j < 2; j++) pA[j] = Arow[j][(t + 1) * 8 + f4];
#pragma unroll
            for (int j = 0; j < 4; j++) pB[j] = Brow[j][(t + 1) * 8 + f4];
        }
        const uint32_t* Ab = Asm[cur];
        const uint32_t* Bb = Bsm[cur];
#pragma unroll
        for (int ks = 0; ks < 4; ks++) {
            int k = ks * 8;
            uint32_t bf[4][2];
#pragma unroll
            for (int nt = 0; nt < 4; nt++) {
                int nc = wn * 32 + nt * 8 + g;
                bf[nt][0] = Bb[nc * G2_LD + k + tig];
                bf[nt][1] = Bb[nc * G2_LD + k + tig + 4];
            }
#pragma unroll
            for (int mt = 0; mt < 2; mt++) {
                int mr = wm * 32 + mt * 16 + g;
                uint32_t a0 = Ab[mr * G2_LD + k + tig];
                uint32_t a1 = Ab[(mr + 8) * G2_LD + k + tig];
                uint32_t a2 = Ab[mr * G2_LD + k + tig + 4];
                uint32_t a3 = Ab[(mr + 8) * G2_LD + k + tig + 4];
#pragma unroll
                for (int nt = 0; nt < 4; nt++)
                    mma_tf32(acc[mt][nt], a0, a1, a2, a3, bf[nt][0], bf[nt][1]);
            }
        }
        if (t + 1 < NT) {
            int nxt = cur ^ 1;
#pragma unroll
            for (int j = 0; j < 2; j++) {
                uint4 u = { f2tf32(pA[j].x), f2tf32(pA[j].y), f2tf32(pA[j].z), f2tf32(pA[j].w) };
                *(uint4*)&Asm[nxt][(q8 + 32 * j) * G2_LD + f4 * 4] = u;
            }
#pragma unroll
            for (int j = 0; j < 4; j++) {
                uint4 u = { f2tf32(pB[j].x), f2tf32(pB[j].y), f2tf32(pB[j].z), f2tf32(pB[j].w) };
                *(uint4*)&Bsm[nxt][(q8 + 32 * j) * G2_LD + f4 * 4] = u;
            }
        }
        __syncthreads();
    }

    float p[2][2] = {};
#pragma unroll
    for (int mt = 0; mt < 2; mt++)
#pragma unroll
        for (int nt = 0; nt < 4; nt++) {
            int c = wn * 32 + nt * 8 + 2 * tig;
            float b0 = b2[c], b1 = b2[c + 1];
            acc[mt][nt][0] += b0; acc[mt][nt][1] += b1;
            acc[mt][nt][2] += b0; acc[mt][nt][3] += b1;
            p[mt][0] += acc[mt][nt][0] * acc[mt][nt][0] + acc[mt][nt][1] * acc[mt][nt][1];
            p[mt][1] += acc[mt][nt][2] * acc[mt][nt][2] + acc[mt][nt][3] * acc[mt][nt][3];
        }
#pragma unroll
    for (int mt = 0; mt < 2; mt++)
#pragma unroll
        for (int rr = 0; rr < 2; rr++) {
            p[mt][rr] += __shfl_xor_sync(~0u, p[mt][rr], 1);
            p[mt][rr] += __shfl_xor_sync(~0u, p[mt][rr], 2);
        }
    float* norms = (float*)sm;
    if (tig == 0) {
#pragma unroll
        for (int mt = 0; mt < 2; mt++)
#pragma unroll
            for (int rr = 0; rr < 2; rr++)
                norms[wn * 64 + wm * 32 + mt * 16 + rr * 8 + g] = p[mt][rr];
    }
    __syncthreads();
#pragma unroll
    for (int mt = 0; mt < 2; mt++)
#pragma unroll
        for (int rr = 0; rr < 2; rr++) {
            int rl = wm * 32 + mt * 16 + rr * 8 + g;
            float tot = norms[rl] + norms[64 + rl] + norms[128 + rl] + norms[192 + rl];
            float rn = 1.f / fmaxf(sqrtf(tot), 1e-12f);
            int row = m0 + rl;
#pragma unroll
            for (int nt = 0; nt < 4; nt++) {
                int c = wn * 32 + nt * 8 + 2 * tig;
                float2 o = { __uint_as_float(f2tf32(acc[mt][nt][rr * 2 + 0] * rn)),
                             __uint_as_float(f2tf32(acc[mt][nt][rr * 2 + 1] * rn)) };
                *(float2*)&Z[(size_t)row * Dn + c] = o;
            }
        }
}

// ---------------- Attention v6: 512 threads (16 warps = 4/SMSP), smem-P, fused decision MLP ----------------
// warps: wq = wid>>3 (q-group of 16 rows), ws = wid&7 (l-subset of 8 in scores; d-subset of 16 in PV)
#define A_LDZ 136
#define A_LDP 68
#define A_ZQW (32 * A_LDZ)                 // 4352 words
#define A_ZBW (64 * A_LDZ)                 // 8704 words
#define PS_OFF (A_ZQW + 2 * A_ZBW)         // 21760
#define ATTN_WORDS (PS_OFF + 32 * A_LDP)   // 23936
#define ATTN_SMEM (ATTN_WORDS * 4)         // 95744 B
#define CAT_LD 264
__global__ void __launch_bounds__(512, 1) attn_fused(
        const float* __restrict__ Zq, const float* __restrict__ Zr,
        const float* __restrict__ W1T, const float* __restrict__ gd, const float* __restrict__ bd,
        const float* __restrict__ b1d, const float* __restrict__ W2d, const float* __restrict__ b2d,
        const float* __restrict__ beta, const float* __restrict__ Wlen, const float* __restrict__ blen,
        float* __restrict__ out) {
    uint32_t* smw = (uint32_t*)dynsm;
    uint32_t* zqb = smw;
    uint32_t* zbuf[2] = { smw + A_ZQW, smw + A_ZQW + A_ZBW };
    uint32_t* ps = smw + PS_OFF;
    __shared__ float zpart[8][32];
    __shared__ float tpart[8][32];
    __shared__ float ent_s[32];
    __shared__ float cos_s[32];

    int tid = threadIdx.x;
    int wid = tid >> 5, lane = tid & 31;
    int wq = wid >> 3, ws = wid & 7;
    int g = lane >> 2, tig = lane & 3;
    int q0 = blockIdx.x * 32;
    int qr = wq * 16;
    const float scale = 0.08838834764831845f;  // 1/sqrt(128)

    uint32_t zq_sb = (uint32_t)__cvta_generic_to_shared(zqb);
    uint32_t zb_sb[2] = { (uint32_t)__cvta_generic_to_shared(zbuf[0]),
                          (uint32_t)__cvta_generic_to_shared(zbuf[1]) };

    // stage zq (32x128) + Zr tile0 (group0); Zr tile1 (group1)
#pragma unroll
    for (int j = 0; j < 2; j++) {
        int i = tid + j * 512, r = i >> 5, c4 = (i & 31) * 4;
        cpa16(zq_sb + (r * A_LDZ + c4) * 4, Zq + (size_t)(q0 + r) * Dn + c4);
    }
#pragma unroll
    for (int j = 0; j < 4; j++) {
        int i = tid + j * 512, r = i >> 5, c4 = (i & 31) * 4;
        cpa16(zb_sb[0] + (r * A_LDZ + c4) * 4, Zr + (size_t)r * Dn + c4);
    }
    CP_COMMIT();
#pragma unroll
    for (int j = 0; j < 4; j++) {
        int i = tid + j * 512, r = i >> 5, c4 = (i & 31) * 4;
        cpa16(zb_sb[1] + (r * A_LDZ + c4) * 4, Zr + (size_t)(64 + r) * Dn + c4);
    }
    CP_COMMIT();
    CP_WAIT1();
    __syncthreads();

    float O[2][4] = {};
    float zs0 = 0.f, zs1 = 0.f, ts0 = 0.f, ts1 = 0.f;
    const int NT = Lnn / 64;  // 64

    // aq reload addresses (conflict-free 8g+tig pattern)
    const uint32_t* aqr0 = &zqb[(qr + g) * A_LDZ + tig];
    const uint32_t* aqr1 = aqr0 + 8 * A_LDZ;

    for (int t = 0; t < NT; t++) {
        int cur = t & 1;
        if (t > 0) {
            CP_WAIT1();
            __syncthreads();
        }
        const uint32_t* zb = zbuf[cur];

        // scores: warp's 8 l-cols, parity-split accumulators
        float sc[2][4] = {};
#pragma unroll
        for (int kt = 0; kt < 16; kt++) {
            uint32_t a0 = aqr0[kt * 8];
            uint32_t a1 = aqr1[kt * 8];
            uint32_t a2 = aqr0[kt * 8 + 4];
            uint32_t a3 = aqr1[kt * 8 + 4];
            int lb = ws * 8 + g;
            uint32_t b0 = zb[lb * A_LDZ + kt * 8 + tig];
            uint32_t b1 = zb[lb * A_LDZ + kt * 8 + tig + 4];
            mma_tf32(sc[kt & 1], a0, a1, a2, a3, b0, b1);
        }

        // exp + entropy + store P (tf32) to ps
        {
            float s0 = (sc[0][0] + sc[1][0]) * scale;
            float s1 = (sc[0][1] + sc[1][1]) * scale;
            float s2 = (sc[0][2] + sc[1][2]) * scale;
            float s3 = (sc[0][3] + sc[1][3]) * scale;
            float p0 = __expf(s0), p1 = __expf(s1), p2 = __expf(s2), p3 = __expf(s3);
            zs0 += p0 + p1; ts0 += p0 * s0 + p1 * s1;
            zs1 += p2 + p3; ts1 += p2 * s2 + p3 * s3;
            int c0 = ws * 8 + 2 * tig;
            ps[(qr + g) * A_LDP + c0] = f2tf32(p0);
            ps[(qr + g) * A_LDP + c0 + 1] = f2tf32(p1);
            ps[(qr + g + 8) * A_LDP + c0] = f2tf32(p2);
            ps[(qr + g + 8) * A_LDP + c0 + 1] = f2tf32(p3);
        }
        __syncthreads();

        // PV: k = all 64 l (8 kt), warp covers d [ws*16, ws*16+16)
#pragma unroll
        for (int kt = 0; kt < 8; kt++) {
            uint32_t ap0 = ps[(qr + g) * A_LDP + kt * 8 + tig];
            uint32_t ap1 = ps[(qr + g + 8) * A_LDP + kt * 8 + tig];
            uint32_t ap2 = ps[(qr + g) * A_LDP + kt * 8 + tig + 4];
            uint32_t ap3 = ps[(qr + g + 8) * A_LDP + kt * 8 + tig + 4];
#pragma unroll
            for (int nt = 0; nt < 2; nt++) {
                int db = ws * 16 + nt * 8 + g;
                uint32_t b0 = zb[(kt * 8 + tig) * A_LDZ + db];
                uint32_t b1 = zb[(kt * 8 + tig + 4) * A_LDZ + db];
                mma_tf32(O[nt], ap0, ap1, ap2, ap3, b0, b1);
            }
        }
        __syncthreads();   // done reading zbuf[cur] and ps

        if (t + 2 < NT) {
            const float* srcp = Zr + (size_t)(t + 2) * 64 * Dn;
#pragma unroll
            for (int j = 0; j < 4; j++) {
                int i = tid + j * 512, r = i >> 5, c4 = (i & 31) * 4;
                cpa16(zb_sb[cur] + (r * A_LDZ + c4) * 4, srcp + (size_t)r * Dn + c4);
            }
        }
        CP_COMMIT();
    }

    // entropy partials over tig quad
    zs0 += __shfl_xor_sync(~0u, zs0, 1); zs0 += __shfl_xor_sync(~0u, zs0, 2);
    zs1 += __shfl_xor_sync(~0u, zs1, 1); zs1 += __shfl_xor_sync(~0u, zs1, 2);
    ts0 += __shfl_xor_sync(~0u, ts0, 1); ts0 += __shfl_xor_sync(~0u, ts0, 2);
    ts1 += __shfl_xor_sync(~0u, ts1, 1); ts1 += __shfl_xor_sync(~0u, ts1, 2);
    if (tig == 0) {
        zpart[ws][qr + g] = zs0; zpart[ws][qr + g + 8] = zs1;
        tpart[ws][qr + g] = ts0; tpart[ws][qr + g + 8] = ts1;
    }

    // O is complete per-warp for its 16 d-columns — single dump, no reduction
    float* Osm = (float*)(smw + A_ZQW);  // 32 x 132 = 4224 words
#pragma unroll
    for (int nt = 0; nt < 2; nt++) {
        int dc = ws * 16 + nt * 8 + 2 * tig;
        Osm[(qr + g) * 132 + dc] = O[nt][0];
        Osm[(qr + g) * 132 + dc + 1] = O[nt][1];
        Osm[(qr + g + 8) * 132 + dc] = O[nt][2];
        Osm[(qr + g + 8) * 132 + dc + 1] = O[nt][3];
    }
    __syncthreads();

    // ===== fused decision MLP =====
    float* cat = (float*)(smw + A_ZQW + 4224);   // 32 x 264 = 8448 words (8576..17024)
    float* part = (float*)(smw + 17024);         // 32 x 128 = 4096 words (17024..21120)
    {
        int row = tid >> 4, hx = tid & 15;       // 16 threads per row, 8 d each
        float4 v[2];
        float sq = 0.f;
#pragma unroll
        for (int j = 0; j < 2; j++) {
            v[j] = *(float4*)&Osm[row * 132 + hx * 8 + j * 4];
            sq += v[j].x * v[j].x + v[j].y * v[j].y + v[j].z * v[j].z + v[j].w * v[j].w;
        }
        sq += __shfl_xor_sync(~0u, sq, 1);
        sq += __shfl_xor_sync(~0u, sq, 2);
        sq += __shfl_xor_sync(~0u, sq, 4);
        sq += __shfl_xor_sync(~0u, sq, 8);
        float rn = 1.f / fmaxf(sqrtf(sq), 1e-12f);
#pragma unroll
        for (int j = 0; j < 2; j++) {
            float4 o = { v[j].x * rn, v[j].y * rn, v[j].z * rn, v[j].w * rn };
            *(float4*)&cat[row * CAT_LD + 128 + hx * 8 + j * 4] = o;
        }
#pragma unroll
        for (int j = 0; j < 2; j++) {
            uint4 u = *(uint4*)&zqb[row * A_LDZ + hx * 8 + j * 4];
            float4 o = { __uint_as_float(u.x), __uint_as_float(u.y),
                         __uint_as_float(u.z), __uint_as_float(u.w) };
            *(float4*)&cat[row * CAT_LD + hx * 8 + j * 4] = o;
        }
        if (hx == 0) {
            float zsum = 0.f, tsum = 0.f;
#pragma unroll
            for (int w2i = 0; w2i < 8; w2i++) { zsum += zpart[w2i][row]; tsum += tpart[w2i][row]; }
            ent_s[row] = logf(zsum) - tsum / zsum;
        }
    }
    __syncthreads();

    // LayerNorm over cat rows: warp handles rows 2*wid, 2*wid+1 (in-place)
    {
#pragma unroll
        for (int rr = 0; rr < 2; rr++) {
            int r = wid * 2 + rr;
            float smv = 0.f, cs = 0.f;
#pragma unroll
            for (int j = 0; j < 8; j++) smv += cat[r * CAT_LD + lane + 32 * j];
#pragma unroll
            for (int j = 0; j < 4; j++) {
                int k = lane + 32 * j;
                cs += cat[r * CAT_LD + k] * cat[r * CAT_LD + 128 + k];
            }
#pragma unroll
            for (int o = 16; o > 0; o >>= 1) {
                smv += __shfl_xor_sync(~0u, smv, o);
                cs += __shfl_xor_sync(~0u, cs, o);
            }
            float mean = smv * (1.f / D2n);
            float vq = 0.f;
#pragma unroll
            for (int j = 0; j < 8; j++) {
                float d = cat[r * CAT_LD + lane + 32 * j] - mean;
                vq += d * d;
            }
#pragma unroll
            for (int o = 16; o > 0; o >>= 1) vq += __shfl_xor_sync(~0u, vq, o);
            float rstd = rsqrtf(vq * (1.f / D2n) + 1e-5f);
#pragma unroll
            for (int j = 0; j < 8; j++) {
                int k = lane + 32 * j;
                cat[r * CAT_LD + k] = (cat[r * CAT_LD + k] - mean) * rstd * gd[k] + bd[k];
            }
            if (lane == 0) cos_s[r] = cs;
        }
    }
    __syncthreads();

    // decision GEMM: thread = (neuron j, row-quarter); 8 rows each
    {
        int j = tid & 127, qtr = tid >> 7;
        float b1 = b1d[j];
        float acc[8];
#pragma unroll
        for (int r = 0; r < 8; r++) acc[r] = b1;
        for (int k = 0; k < D2n; k++) {
            float w1 = W1T[k * 128 + j];
#pragma unroll
            for (int r = 0; r < 8; r++)
                acc[r] += cat[(qtr * 8 + r) * CAT_LD + k] * w1;
        }
        float w2 = W2d[j];
#pragma unroll
        for (int r = 0; r < 8; r++) {
            float v = acc[r];
            v = 0.5f * v * (1.f + erff(v * 0.7071067811865475f));
            part[(qtr * 8 + r) * 128 + j] = v * w2;
        }
    }
    __syncthreads();

    // reduce + heads
    {
        int row = tid >> 4, hx = tid & 15;
        float s = 0.f;
#pragma unroll
        for (int i = 0; i < 8; i++) s += part[row * 128 + hx * 8 + i];
        s += __shfl_xor_sync(~0u, s, 1);
        s += __shfl_xor_sync(~0u, s, 2);
        s += __shfl_xor_sync(~0u, s, 4);
        s += __shfl_xor_sync(~0u, s, 8);
        if (hx == 0) {
            float raw_logit = s + b2d[0];
            float u = ent_s[row] * (1.f / logf((float)Lnn));
            float cs = cos_s[row];
            float dl = Wlen[0] * cs + Wlen[1] * u + blen[0];
            float lf = tanhf(dl);
            float dt = beta[0] * u + beta[1] * lf;
            dt = fminf(fmaxf(dt, -0.5f), 0.5f);
            out[q0 + row] = raw_logit;
            out[Bn + q0 + row] = dt;
        }
    }
}

// ---------------- host launcher ----------------
extern "C" void kernel_launch(void* const* d_in, const int* in_sizes, int n_in,
                              void* d_out, int out_size) {
    const float* q    = (const float*)d_in[0];
    const float* R    = (const float*)d_in[1];
    const float* lnqg = (const float*)d_in[2];
    const float* lnqb = (const float*)d_in[3];
    const float* W1q  = (const float*)d_in[4];
    const float* b1q  = (const float*)d_in[5];
    const float* W2q  = (const float*)d_in[6];
    const float* b2q  = (const float*)d_in[7];
    const float* lnrg = (const float*)d_in[8];
    const float* lnrb = (const float*)d_in[9];
    const float* W1r  = (const float*)d_in[10];
    const float* b1r  = (const float*)d_in[11];
    const float* W2r  = (const float*)d_in[12];
    const float* b2r  = (const float*)d_in[13];
    const float* lndg = (const float*)d_in[14];
    const float* lndb = (const float*)d_in[15];
    const float* W1d  = (const float*)d_in[16];
    const float* b1d  = (const float*)d_in[17];
    const float* W2d  = (const float*)d_in[18];
    const float* b2d  = (const float*)d_in[19];
    const float* beta = (const float*)d_in[20];
    const float* Wlen = (const float*)d_in[21];
    const float* blen = (const float*)d_in[22];
    float* out = (float*)d_out;

    float *hb, *zq, *zr, *mu, *rs, *w1t;
    cudaGetSymbolAddress((void**)&hb, g_Hb);
    cudaGetSymbolAddress((void**)&zq, g_Zq);
    cudaGetSymbolAddress((void**)&zr, g_Zr);
    cudaGetSymbolAddress((void**)&mu, g_mu);
    cudaGetSymbolAddress((void**)&rs, g_rs);
    cudaGetSymbolAddress((void**)&w1t, g_W1T);

    cudaFuncSetAttribute(gemm1_both, cudaFuncAttributeMaxDynamicSharedMemorySize, G1_SMEM);
    cudaFuncSetAttribute(gemm2_mma, cudaFuncAttributeMaxDynamicSharedMemorySize, G2_SMEM);
    cudaFuncSetAttribute(attn_fused, cudaFuncAttributeMaxDynamicSharedMemorySize, ATTN_SMEM);

    rs_tw<<<dim3(Bn / 8, 3), 256>>>(q, R, mu, rs, W1d, w1t);
    gemm1_both<<<dim3(D2n / 64, Bn / 128, 2), 256, G1_SMEM>>>(
        q, R, W1q, W1r, lnqg, lnrg, lnqb, lnrb, b1q, b1r, mu, rs, hb);
    gemm2_mma<<<dim3(Bn / 64, 2), 256, G2_SMEM>>>(hb, W2q, W2r, b2q, b2r, zq, zr);
    attn_fused<<<Bn / 32, 512, ATTN_SMEM>>>(zq, zr, w1t, lndg, lndb, b1d, W2d, b2d,
                                            beta, Wlen, blen, out);
}

// round 16
// speedup vs baseline: 1.2247x; 1.2247x over previous
#include <cuda_runtime.h>
#include <math.h>
#include <stdint.h>

#define Bn   4096
#define Lnn  4096
#define Hn   2048
#define Dn   128
#define D2n  256

// ---------------- scratch ----------------
__device__ float g_Hb[(size_t)2 * Bn * D2n];
__device__ float g_Zq[(size_t)Bn * Dn];
__device__ float g_Zr[(size_t)Lnn * Dn];
__device__ float g_mu[2 * Bn];
__device__ float g_rs[2 * Bn];
__device__ float g_W1T[128 * 256];

extern __shared__ char dynsm[];

// ================= helpers =================
__device__ __forceinline__ uint32_t f2tf32(float f) {
    uint32_t r;
    asm("cvt.rna.tf32.f32 %0, %1;" : "=r"(r) : "f"(f));
    return r;
}

__device__ __forceinline__ void mma_tf32(float* c, uint32_t a0, uint32_t a1, uint32_t a2, uint32_t a3,
                                         uint32_t b0, uint32_t b1) {
    asm volatile(
        "mma.sync.aligned.m16n8k8.row.col.f32.tf32.tf32.f32 "
        "{%0,%1,%2,%3}, {%4,%5,%6,%7}, {%8,%9}, {%0,%1,%2,%3};"
        : "+f"(c[0]), "+f"(c[1]), "+f"(c[2]), "+f"(c[3])
        : "r"(a0), "r"(a1), "r"(a2), "r"(a3), "r"(b0), "r"(b1));
}

__device__ __forceinline__ void cpa16(uint32_t dst, const void* src) {
    asm volatile("cp.async.cg.shared.global [%0], [%1], 16;" :: "r"(dst), "l"(src));
}
#define CP_COMMIT() asm volatile("cp.async.commit_group;" ::: "memory")
#define CP_WAIT1()  asm volatile("cp.async.wait_group 1;" ::: "memory")

// ---------------- row stats (z=0,1) + W1 transpose (z=2) in one launch ----------------
__global__ void rs_tw(const float* __restrict__ xq, const float* __restrict__ xr,
                      float* __restrict__ mu, float* __restrict__ rs,
                      const float* __restrict__ W1d, float* __restrict__ W1T) {
    int z = blockIdx.y;
    if (z == 2) {
        if (blockIdx.x >= 32) return;
        __shared__ float tsm[32][33];
        int bx = blockIdx.x & 7, by = blockIdx.x >> 3;
        int x = threadIdx.x & 31, y = threadIdx.x >> 5;  // 32 x 8
#pragma unroll
        for (int i = 0; i < 32; i += 8)
            tsm[y + i][x] = W1d[(by * 32 + y + i) * 256 + bx * 32 + x];
        __syncthreads();
#pragma unroll
        for (int i = 0; i < 32; i += 8)
            W1T[(bx * 32 + y + i) * 128 + by * 32 + x] = tsm[x][y + i];
        return;
    }
    const float* x = z ? xr : xq;
    int wid = threadIdx.x >> 5, lane = threadIdx.x & 31;
    int row = blockIdx.x * 8 + wid;
    const float4* xrow = (const float4*)(x + (size_t)row * Hn);
    float s = 0.f, sq = 0.f;
    for (int k = lane; k < Hn / 4; k += 32) {
        float4 v = xrow[k];
        s += v.x + v.y + v.z + v.w;
        sq += v.x * v.x + v.y * v.y + v.z * v.z + v.w * v.w;
    }
#pragma unroll
    for (int o = 16; o > 0; o >>= 1) {
        s += __shfl_xor_sync(~0u, s, o);
        sq += __shfl_xor_sync(~0u, sq, o);
    }
    if (lane == 0) {
        float m = s * (1.f / Hn);
        float var = sq * (1.f / Hn) - m * m;
        mu[z * Bn + row] = m;
        rs[z * Bn + row] = rsqrtf(var + 1e-5f);
    }
}

// ---------------- GEMM1 v2 (tf32 mma, BM=128, BN=128) + fused LN + GELU ----------------
#define G1_LD 36
#define G1_AS (128 * G1_LD)
#define G1_BS (128 * G1_LD)
#define G1_SMEM ((2 * G1_AS + 2 * G1_BS) * 4)   // 73728 B

__global__ void __launch_bounds__(256, 1) gemm1_both(
        const float* __restrict__ Aq, const float* __restrict__ Ar,
        const float* __restrict__ Wq, const float* __restrict__ Wr,
        const float* __restrict__ gq, const float* __restrict__ gr,
        const float* __restrict__ bq, const float* __restrict__ br,
        const float* __restrict__ biasq, const float* __restrict__ biasr,
        const float* __restrict__ mean, const float* __restrict__ rstd,
        float* __restrict__ Cb) {
    int z = blockIdx.z;
    const float* A = z ? Ar : Aq;
    const float* W = z ? Wr : Wq;
    const float* gamma = z ? gr : gq;
    const float* beta = z ? br : bq;
    const float* bias = z ? biasr : biasq;
    float* C = Cb + (size_t)z * Bn * D2n;
    const float* mub = mean + z * Bn;
    const float* rsb = rstd + z * Bn;

    uint32_t* sm = (uint32_t*)dynsm;
    uint32_t* Asm[2] = { sm, sm + G1_AS };
    uint32_t* Bsm[2] = { sm + 2 * G1_AS, sm + 2 * G1_AS + G1_BS };

    int tid = threadIdx.x;
    int wid = tid >> 5, lane = tid & 31;
    int wm = wid & 3, wn = wid >> 2;     // 4 m-warps x 2 n-warps, warptile 32x64
    int g = lane >> 2, tig = lane & 3;
    int m0 = blockIdx.y * 128, n0 = blockIdx.x * 128;
    int q = tid >> 3, f4 = tid & 7;

    const float4* Arow[4];
    float mu[4], rsd[4];
#pragma unroll
    for (int j = 0; j < 4; j++) {
        int r = m0 + q + 32 * j;
        Arow[j] = (const float4*)(A + (size_t)r * Hn);
        mu[j] = mub[r];
        rsd[j] = rsb[r];
    }
    const float4* Brow[4];
#pragma unroll
    for (int j = 0; j < 4; j++) Brow[j] = (const float4*)(W + (size_t)(n0 + q + 32 * j) * Hn);
    const float4* g4p = (const float4*)gamma;
    const float4* b4p = (const float4*)beta;

    float acc[2][8][4] = {};
    float4 pA[4], pB[4], pG, pBt;

    const int NT = Hn / 32;  // 64

    pG = g4p[f4]; pBt = b4p[f4];
#pragma unroll
    for (int j = 0; j < 4; j++) { pA[j] = Arow[j][f4]; pB[j] = Brow[j][f4]; }
#pragma unroll
    for (int j = 0; j < 4; j++) {
        float x0 = (pA[j].x - mu[j]) * rsd[j] * pG.x + pBt.x;
        float x1 = (pA[j].y - mu[j]) * rsd[j] * pG.y + pBt.y;
        float x2 = (pA[j].z - mu[j]) * rsd[j] * pG.z + pBt.z;
        float x3 = (pA[j].w - mu[j]) * rsd[j] * pG.w + pBt.w;
        uint4 ua = { f2tf32(x0), f2tf32(x1), f2tf32(x2), f2tf32(x3) };
        uint4 ub = { f2tf32(pB[j].x), f2tf32(pB[j].y), f2tf32(pB[j].z), f2tf32(pB[j].w) };
        *(uint4*)&Asm[0][(q + 32 * j) * G1_LD + f4 * 4] = ua;
        *(uint4*)&Bsm[0][(q + 32 * j) * G1_LD + f4 * 4] = ub;
    }
    __syncthreads();

    for (int t = 0; t < NT; t++) {
        int cur = t & 1;
        if (t + 1 < NT) {
            pG = g4p[(t + 1) * 8 + f4]; pBt = b4p[(t + 1) * 8 + f4];
#pragma unroll
            for (int j = 0; j < 4; j++) {
                pA[j] = Arow[j][(t + 1) * 8 + f4];
                pB[j] = Brow[j][(t + 1) * 8 + f4];
            }
        }
        const uint32_t* Ab = Asm[cur];
        const uint32_t* Bb = Bsm[cur];
#pragma unroll
        for (int ks = 0; ks < 4; ks++) {
            int k = ks * 8;
            uint32_t bf[8][2];
#pragma unroll
            for (int nt = 0; nt < 8; nt++) {
                int nc = wn * 64 + nt * 8 + g;
                bf[nt][0] = Bb[nc * G1_LD + k + tig];
                bf[nt][1] = Bb[nc * G1_LD + k + tig + 4];
            }
#pragma unroll
            for (int mt = 0; mt < 2; mt++) {
                int mr = wm * 32 + mt * 16 + g;
                uint32_t a0 = Ab[mr * G1_LD + k + tig];
                uint32_t a1 = Ab[(mr + 8) * G1_LD + k + tig];
                uint32_t a2 = Ab[mr * G1_LD + k + tig + 4];
                uint32_t a3 = Ab[(mr + 8) * G1_LD + k + tig + 4];
#pragma unroll
                for (int nt = 0; nt < 8; nt++)
                    mma_tf32(acc[mt][nt], a0, a1, a2, a3, bf[nt][0], bf[nt][1]);
            }
        }
        if (t + 1 < NT) {
            int nxt = cur ^ 1;
#pragma unroll
            for (int j = 0; j < 4; j++) {
                float x0 = (pA[j].x - mu[j]) * rsd[j] * pG.x + pBt.x;
                float x1 = (pA[j].y - mu[j]) * rsd[j] * pG.y + pBt.y;
                float x2 = (pA[j].z - mu[j]) * rsd[j] * pG.z + pBt.z;
                float x3 = (pA[j].w - mu[j]) * rsd[j] * pG.w + pBt.w;
                uint4 ua = { f2tf32(x0), f2tf32(x1), f2tf32(x2), f2tf32(x3) };
                uint4 ub = { f2tf32(pB[j].x), f2tf32(pB[j].y), f2tf32(pB[j].z), f2tf32(pB[j].w) };
                *(uint4*)&Asm[nxt][(q + 32 * j) * G1_LD + f4 * 4] = ua;
                *(uint4*)&Bsm[nxt][(q + 32 * j) * G1_LD + f4 * 4] = ub;
            }
        }
        __syncthreads();
    }

#pragma unroll
    for (int mt = 0; mt < 2; mt++) {
#pragma unroll
        for (int nt = 0; nt < 8; nt++) {
            int n = n0 + wn * 64 + nt * 8 + 2 * tig;
            float bv0 = bias[n], bv1 = bias[n + 1];
#pragma unroll
            for (int rr = 0; rr < 2; rr++) {
                int m = m0 + wm * 32 + mt * 16 + g + rr * 8;
                float v0 = acc[mt][nt][rr * 2 + 0] + bv0;
                float v1 = acc[mt][nt][rr * 2 + 1] + bv1;
                v0 = 0.5f * v0 * (1.f + erff(v0 * 0.7071067811865475f));
                v1 = 0.5f * v1 * (1.f + erff(v1 * 0.7071067811865475f));
                float2 o = {v0, v1};
                *(float2*)(C + (size_t)m * D2n + n) = o;
            }
        }
    }
}

// ---------------- GEMM2 via tf32 mma + fused bias + l2norm. BM=64, grid (64, 2) ----------------
#define G2_LD 36
#define G2_AW (64 * G2_LD)
#define G2_BW (128 * G2_LD)
#define G2_SMEM ((2 * G2_AW + 2 * G2_BW) * 4)

__global__ void __launch_bounds__(256, 2) gemm2_mma(
        const float* __restrict__ Hb,
        const float* __restrict__ W2q, const float* __restrict__ W2r,
        const float* __restrict__ b2q, const float* __restrict__ b2r,
        float* __restrict__ Zq, float* __restrict__ Zr) {
    int z = blockIdx.y;
    const float* Hin = Hb + (size_t)z * Bn * D2n;
    const float* W2 = z ? W2r : W2q;
    const float* b2 = z ? b2r : b2q;
    float* Z = z ? Zr : Zq;

    uint32_t* sm = (uint32_t*)dynsm;
    uint32_t* Asm[2] = { sm, sm + G2_AW };
    uint32_t* Bsm[2] = { sm + 2 * G2_AW, sm + 2 * G2_AW + G2_BW };

    int tid = threadIdx.x;
    int wid = tid >> 5, lane = tid & 31;
    int wm = wid & 1, wn = wid >> 1;
    int g = lane >> 2, tig = lane & 3;
    int m0 = blockIdx.x * 64;
    int q8 = tid >> 3, f4 = tid & 7;

    const float4* Arow[2];
    const float4* Brow[4];
#pragma unroll
    for (int j = 0; j < 2; j++) Arow[j] = (const float4*)(Hin + (size_t)(m0 + q8 + 32 * j) * D2n);
#pragma unroll
    for (int j = 0; j < 4; j++) Brow[j] = (const float4*)(W2 + (size_t)(q8 + 32 * j) * D2n);

    float acc[2][4][4] = {};
    float4 pA[2], pB[4];
    const int NT = D2n / 32;  // 8

#pragma unroll
    for (int j = 0; j < 2; j++) pA[j] = Arow[j][f4];
#pragma unroll
    for (int j = 0; j < 4; j++) pB[j] = Brow[j][f4];
#pragma unroll
    for (int j = 0; j < 2; j++) {
        uint4 u = { f2tf32(pA[j].x), f2tf32(pA[j].y), f2tf32(pA[j].z), f2tf32(pA[j].w) };
        *(uint4*)&Asm[0][(q8 + 32 * j) * G2_LD + f4 * 4] = u;
    }
#pragma unroll
    for (int j = 0; j < 4; j++) {
        uint4 u = { f2tf32(pB[j].x), f2tf32(pB[j].y), f2tf32(pB[j].z), f2tf32(pB[j].w) };
        *(uint4*)&Bsm[0][(q8 + 32 * j) * G2_LD + f4 * 4] = u;
    }
    __syncthreads();

    for (int t = 0; t < NT; t++) {
        int cur = t & 1;
        if (t + 1 < NT) {
#pragma unroll
            for (int j = 0; j < 2; j++) pA[j] = Arow[j][(t + 1) * 8 + f4];
#pragma unroll
            for (int j = 0; j < 4; j++) pB[j] = Brow[j][(t + 1) * 8 + f4];
        }
        const uint32_t* Ab = Asm[cur];
        const uint32_t* Bb = Bsm[cur];
#pragma unroll
        for (int ks = 0; ks < 4; ks++) {
            int k = ks * 8;
            uint32_t bf[4][2];
#pragma unroll
            for (int nt = 0; nt < 4; nt++) {
                int nc = wn * 32 + nt * 8 + g;
                bf[nt][0] = Bb[nc * G2_LD + k + tig];
                bf[nt][1] = Bb[nc * G2_LD + k + tig + 4];
            }
#pragma unroll
            for (int mt = 0; mt < 2; mt++) {
                int mr = wm * 32 + mt * 16 + g;
                uint32_t a0 = Ab[mr * G2_LD + k + tig];
                uint32_t a1 = Ab[(mr + 8) * G2_LD + k + tig];
                uint32_t a2 = Ab[mr * G2_LD + k + tig + 4];
                uint32_t a3 = Ab[(mr + 8) * G2_LD + k + tig + 4];
#pragma unroll
                for (int nt = 0; nt < 4; nt++)
                    mma_tf32(acc[mt][nt], a0, a1, a2, a3, bf[nt][0], bf[nt][1]);
            }
        }
        if (t + 1 < NT) {
            int nxt = cur ^ 1;
#pragma unroll
            for (int j = 0; j < 2; j++) {
                uint4 u = { f2tf32(pA[j].x), f2tf32(pA[j].y), f2tf32(pA[j].z), f2tf32(pA[j].w) };
                *(uint4*)&Asm[nxt][(q8 + 32 * j) * G2_LD + f4 * 4] = u;
            }
#pragma unroll
            for (int j = 0; j < 4; j++) {
                uint4 u = { f2tf32(pB[j].x), f2tf32(pB[j].y), f2tf32(pB[j].z), f2tf32(pB[j].w) };
                *(uint4*)&Bsm[nxt][(q8 + 32 * j) * G2_LD + f4 * 4] = u;
            }
        }
        __syncthreads();
    }

    float p[2][2] = {};
#pragma unroll
    for (int mt = 0; mt < 2; mt++)
#pragma unroll
        for (int nt = 0; nt < 4; nt++) {
            int c = wn * 32 + nt * 8 + 2 * tig;
            float b0 = b2[c], b1 = b2[c + 1];
            acc[mt][nt][0] += b0; acc[mt][nt][1] += b1;
            acc[mt][nt][2] += b0; acc[mt][nt][3] += b1;
            p[mt][0] += acc[mt][nt][0] * acc[mt][nt][0] + acc[mt][nt][1] * acc[mt][nt][1];
            p[mt][1] += acc[mt][nt][2] * acc[mt][nt][2] + acc[mt][nt][3] * acc[mt][nt][3];
        }
#pragma unroll
    for (int mt = 0; mt < 2; mt++)
#pragma unroll
        for (int rr = 0; rr < 2; rr++) {
            p[mt][rr] += __shfl_xor_sync(~0u, p[mt][rr], 1);
            p[mt][rr] += __shfl_xor_sync(~0u, p[mt][rr], 2);
        }
    float* norms = (float*)sm;
    if (tig == 0) {
#pragma unroll
        for (int mt = 0; mt < 2; mt++)
#pragma unroll
            for (int rr = 0; rr < 2; rr++)
                norms[wn * 64 + wm * 32 + mt * 16 + rr * 8 + g] = p[mt][rr];
    }
    __syncthreads();
#pragma unroll
    for (int mt = 0; mt < 2; mt++)
#pragma unroll
        for (int rr = 0; rr < 2; rr++) {
            int rl = wm * 32 + mt * 16 + rr * 8 + g;
            float tot = norms[rl] + norms[64 + rl] + norms[128 + rl] + norms[192 + rl];
            float rn = 1.f / fmaxf(sqrtf(tot), 1e-12f);
            int row = m0 + rl;
#pragma unroll
            for (int nt = 0; nt < 4; nt++) {
                int c = wn * 32 + nt * 8 + 2 * tig;
                float2 o = { __uint_as_float(f2tf32(acc[mt][nt][rr * 2 + 0] * rn)),
                             __uint_as_float(f2tf32(acc[mt][nt][rr * 2 + 1] * rn)) };
                *(float2*)&Z[(size_t)row * Dn + c] = o;
            }
        }
}

// ---------------- Attention (round-14 best) + fused decision MLP epilogue ----------------
#define A_LDZ 136
#define A_ZQW (32 * A_LDZ)
#define A_ZBW (64 * A_LDZ)
#define ATTN_SMEM ((A_ZQW + 2 * A_ZBW) * 4)
#define CAT_LD 264
__global__ void __launch_bounds__(256, 1) attn_fused(
        const float* __restrict__ Zq, const float* __restrict__ Zr,
        const float* __restrict__ W1T, const float* __restrict__ gd, const float* __restrict__ bd,
        const float* __restrict__ b1d, const float* __restrict__ W2d, const float* __restrict__ b2d,
        const float* __restrict__ beta, const float* __restrict__ Wlen, const float* __restrict__ blen,
        float* __restrict__ out) {
    uint32_t* smw = (uint32_t*)dynsm;
    uint32_t* zqb = smw;
    uint32_t* zbuf[2] = { smw + A_ZQW, smw + A_ZQW + A_ZBW };
    __shared__ float zpart[4][32];
    __shared__ float tpart[4][32];
    __shared__ float ent_s[32];
    __shared__ float cos_s[32];

    int tid = threadIdx.x;
    int wid = tid >> 5, lane = tid & 31;
    int wq = wid >> 2, ws = wid & 3;
    int g = lane >> 2, tig = lane & 3;
    int q0 = blockIdx.x * 32;
    int qr = wq * 16;
    const float scale = 0.08838834764831845f;  // 1/sqrt(128)

    uint32_t zq_sb = (uint32_t)__cvta_generic_to_shared(zqb);
    uint32_t zb_sb[2] = { (uint32_t)__cvta_generic_to_shared(zbuf[0]),
                          (uint32_t)__cvta_generic_to_shared(zbuf[1]) };

#pragma unroll
    for (int j = 0; j < 4; j++) {
        int i = tid + j * 256, r = i >> 5, c4 = (i & 31) * 4;
        cpa16(zq_sb + (r * A_LDZ + c4) * 4, Zq + (size_t)(q0 + r) * Dn + c4);
    }
#pragma unroll
    for (int j = 0; j < 8; j++) {
        int i = tid + j * 256, r = i >> 5, c4 = (i & 31) * 4;
        cpa16(zb_sb[0] + (r * A_LDZ + c4) * 4, Zr + (size_t)r * Dn + c4);
    }
    CP_COMMIT();
#pragma unroll
    for (int j = 0; j < 8; j++) {
        int i = tid + j * 256, r = i >> 5, c4 = (i & 31) * 4;
        cpa16(zb_sb[1] + (r * A_LDZ + c4) * 4, Zr + (size_t)(64 + r) * Dn + c4);
    }
    CP_COMMIT();
    CP_WAIT1();
    __syncthreads();

    // persistent A fragments of Zq for scores
    uint32_t aq[16][4];
#pragma unroll
    for (int kt = 0; kt < 16; kt++) {
        aq[kt][0] = zqb[(qr + g) * A_LDZ + kt * 8 + tig];
        aq[kt][1] = zqb[(qr + g + 8) * A_LDZ + kt * 8 + tig];
        aq[kt][2] = zqb[(qr + g) * A_LDZ + kt * 8 + tig + 4];
        aq[kt][3] = zqb[(qr + g + 8) * A_LDZ + kt * 8 + tig + 4];
    }

    float O[16][4] = {};
    float zs0 = 0.f, zs1 = 0.f, ts0 = 0.f, ts1 = 0.f;
    const int NT = Lnn / 64;  // 64

    for (int t = 0; t < NT; t++) {
        int cur = t & 1;
        if (t > 0) {
            CP_WAIT1();
            __syncthreads();
        }
        const uint32_t* zb = zbuf[cur];

        // scores: warp's 16 l-cols, parity-split accumulators
        float sc[2][2][4] = {};
#pragma unroll
        for (int kt = 0; kt < 16; kt++) {
            int par = kt & 1;
#pragma unroll
            for (int nt = 0; nt < 2; nt++) {
                int lb = ws * 16 + nt * 8 + g;
                uint32_t b0 = zb[lb * A_LDZ + kt * 8 + tig];
                uint32_t b1 = zb[lb * A_LDZ + kt * 8 + tig + 4];
                mma_tf32(sc[nt][par], aq[kt][0], aq[kt][1], aq[kt][2], aq[kt][3], b0, b1);
            }
        }

        // exp in-register + entropy accumulation
        float pv[2][4];
#pragma unroll
        for (int nt = 0; nt < 2; nt++) {
            float s0 = (sc[nt][0][0] + sc[nt][1][0]) * scale;
            float s1 = (sc[nt][0][1] + sc[nt][1][1]) * scale;
            float s2 = (sc[nt][0][2] + sc[nt][1][2]) * scale;
            float s3 = (sc[nt][0][3] + sc[nt][1][3]) * scale;
            float p0 = __expf(s0), p1 = __expf(s1), p2 = __expf(s2), p3 = __expf(s3);
            zs0 += p0 + p1; ts0 += p0 * s0 + p1 * s1;
            zs1 += p2 + p3; ts1 += p2 * s2 + p3 * s3;
            pv[nt][0] = p0; pv[nt][1] = p1; pv[nt][2] = p2; pv[nt][3] = p3;
        }

        // shuffle P (accumulator layout) into A-fragment layout, cvt tf32
        uint32_t ap[2][4];
        int src = 4 * g + (tig >> 1);
        bool odd = (tig & 1);
#pragma unroll
        for (int j = 0; j < 2; j++) {
            float q0v = __shfl_sync(~0u, pv[j][0], src);
            float q1v = __shfl_sync(~0u, pv[j][1], src);
            float q2v = __shfl_sync(~0u, pv[j][2], src);
            float q3v = __shfl_sync(~0u, pv[j][3], src);
            float r0v = __shfl_sync(~0u, pv[j][0], src + 2);
            float r1v = __shfl_sync(~0u, pv[j][1], src + 2);
            float r2v = __shfl_sync(~0u, pv[j][2], src + 2);
            float r3v = __shfl_sync(~0u, pv[j][3], src + 2);
            ap[j][0] = f2tf32(odd ? q1v : q0v);
            ap[j][1] = f2tf32(odd ? q3v : q2v);
            ap[j][2] = f2tf32(odd ? r1v : r0v);
            ap[j][3] = f2tf32(odd ? r3v : r2v);
        }

        // PV: k-dim = warp's 16 l-cols (2 steps), all 128 d (16 n-tiles)
#pragma unroll
        for (int j = 0; j < 2; j++) {
            int lr = ws * 16 + j * 8;
#pragma unroll
            for (int nt = 0; nt < 16; nt++) {
                int db = nt * 8 + g;
                uint32_t b0 = zb[(lr + tig) * A_LDZ + db];
                uint32_t b1 = zb[(lr + tig + 4) * A_LDZ + db];
                mma_tf32(O[nt], ap[j][0], ap[j][1], ap[j][2], ap[j][3], b0, b1);
            }
        }
        __syncthreads();

        if (t + 2 < NT) {
            const float* srcp = Zr + (size_t)(t + 2) * 64 * Dn;
#pragma unroll
            for (int j = 0; j < 8; j++) {
                int i = tid + j * 256, r = i >> 5, c4 = (i & 31) * 4;
                cpa16(zb_sb[cur] + (r * A_LDZ + c4) * 4, srcp + (size_t)r * Dn + c4);
            }
        }
        CP_COMMIT();
    }

    // entropy partials
    zs0 += __shfl_xor_sync(~0u, zs0, 1); zs0 += __shfl_xor_sync(~0u, zs0, 2);
    zs1 += __shfl_xor_sync(~0u, zs1, 1); zs1 += __shfl_xor_sync(~0u, zs1, 2);
    ts0 += __shfl_xor_sync(~0u, ts0, 1); ts0 += __shfl_xor_sync(~0u, ts0, 2);
    ts1 += __shfl_xor_sync(~0u, ts1, 1); ts1 += __shfl_xor_sync(~0u, ts1, 2);
    if (tig == 0) {
        zpart[ws][qr + g] = zs0; zpart[ws][qr + g + 8] = zs1;
        tpart[ws][qr + g] = ts0; tpart[ws][qr + g + 8] = ts1;
    }

    // dump per-warp O into smem [ws][32][132]
    float* Osm = (float*)zbuf[0];
#pragma unroll
    for (int nt = 0; nt < 16; nt++) {
        int dc = nt * 8 + 2 * tig;
        float* base = Osm + ws * 32 * 132;
        base[(qr + g) * 132 + dc] = O[nt][0];
        base[(qr + g) * 132 + dc + 1] = O[nt][1];
        base[(qr + g + 8) * 132 + dc] = O[nt][2];
        base[(qr + g + 8) * 132 + dc + 1] = O[nt][3];
    }
    __syncthreads();

    // ===== fused decision MLP for this CTA's 32 rows =====
    float* cat = (float*)zbuf[1];
    {
        int row = tid >> 3, oct = tid & 7;
        float4 v[4];
        float sq = 0.f;
#pragma unroll
        for (int j = 0; j < 4; j++) {
            int off = row * 132 + oct * 16 + j * 4;
            float4 a0 = *(float4*)&Osm[off];
            float4 a1 = *(float4*)&Osm[32 * 132 + off];
            float4 a2 = *(float4*)&Osm[2 * 32 * 132 + off];
            float4 a3 = *(float4*)&Osm[3 * 32 * 132 + off];
            float4 a = { a0.x + a1.x + a2.x + a3.x, a0.y + a1.y + a2.y + a3.y,
                         a0.z + a1.z + a2.z + a3.z, a0.w + a1.w + a2.w + a3.w };
            v[j] = a;
            sq += a.x * a.x + a.y * a.y + a.z * a.z + a.w * a.w;
        }
        sq += __shfl_xor_sync(~0u, sq, 1);
        sq += __shfl_xor_sync(~0u, sq, 2);
        sq += __shfl_xor_sync(~0u, sq, 4);
        float rn = 1.f / fmaxf(sqrtf(sq), 1e-12f);
#pragma unroll
        for (int j = 0; j < 4; j++) {
            float4 o = { v[j].x * rn, v[j].y * rn, v[j].z * rn, v[j].w * rn };
            *(float4*)&cat[row * CAT_LD + 128 + oct * 16 + j * 4] = o;
        }
#pragma unroll
        for (int j = 0; j < 4; j++) {
            uint4 u = *(uint4*)&zqb[row * A_LDZ + oct * 16 + j * 4];
            float4 o = { __uint_as_float(u.x), __uint_as_float(u.y),
                         __uint_as_float(u.z), __uint_as_float(u.w) };
            *(float4*)&cat[row * CAT_LD + oct * 16 + j * 4] = o;
        }
        if (oct == 0) {
            float zsum = zpart[0][row] + zpart[1][row] + zpart[2][row] + zpart[3][row];
            float tsum = tpart[0][row] + tpart[1][row] + tpart[2][row] + tpart[3][row];
            ent_s[row] = logf(zsum) - tsum / zsum;
        }
    }
    __syncthreads();

    // LayerNorm over cat rows: warp w handles rows 4w..4w+3 (in-place)
    {
        int w = wid;
#pragma unroll
        for (int rr = 0; rr < 4; rr++) {
            int r = w * 4 + rr;
            float smv = 0.f, cs = 0.f;
#pragma unroll
            for (int j = 0; j < 8; j++) smv += cat[r * CAT_LD + lane + 32 * j];
#pragma unroll
            for (int j = 0; j < 4; j++) {
                int k = lane + 32 * j;
                cs += cat[r * CAT_LD + k] * cat[r * CAT_LD + 128 + k];
            }
#pragma unroll
            for (int o = 16; o > 0; o >>= 1) {
                smv += __shfl_xor_sync(~0u, smv, o);
                cs += __shfl_xor_sync(~0u, cs, o);
            }
            float mean = smv * (1.f / D2n);
            float vq = 0.f;
#pragma unroll
            for (int j = 0; j < 8; j++) {
                float d = cat[r * CAT_LD + lane + 32 * j] - mean;
                vq += d * d;
            }
#pragma unroll
            for (int o = 16; o > 0; o >>= 1) vq += __shfl_xor_sync(~0u, vq, o);
            float rstd = rsqrtf(vq * (1.f / D2n) + 1e-5f);
#pragma unroll
            for (int j = 0; j < 8; j++) {
                int k = lane + 32 * j;
                cat[r * CAT_LD + k] = (cat[r * CAT_LD + k] - mean) * rstd * gd[k] + bd[k];
            }
            if (lane == 0) cos_s[r] = cs;
        }
    }
    __syncthreads();

    // decision GEMM: thread = (neuron j, row-half); 16 rows each
    float* part = (float*)zqb;
    {
        int j = tid & 127, half = tid >> 7;
        float b1 = b1d[j];
        float acc[16];
#pragma unroll
        for (int r = 0; r < 16; r++) acc[r] = b1;
        for (int k = 0; k < D2n; k++) {
            float w1 = W1T[k * 128 + j];
#pragma unroll
            for (int r = 0; r < 16; r++)
                acc[r] += cat[(half * 16 + r) * CAT_LD + k] * w1;
        }
        float w2 = W2d[j];
#pragma unroll
        for (int r = 0; r < 16; r++) {
            float v = acc[r];
            v = 0.5f * v * (1.f + erff(v * 0.7071067811865475f));
            part[(half * 16 + r) * 128 + j] = v * w2;
        }
    }
    __syncthreads();

    // reduce + heads
    {
        int row = tid >> 3, oct = tid & 7;
        float s = 0.f;
#pragma unroll
        for (int i = 0; i < 16; i++) s += part[row * 128 + oct * 16 + i];
        s += __shfl_xor_sync(~0u, s, 1);
        s += __shfl_xor_sync(~0u, s, 2);
        s += __shfl_xor_sync(~0u, s, 4);
        if (oct == 0) {
            float raw_logit = s + b2d[0];
            float u = ent_s[row] * (1.f / logf((float)Lnn));
            float cs = cos_s[row];
            float dl = Wlen[0] * cs + Wlen[1] * u + blen[0];
            float lf = tanhf(dl);
            float dt = beta[0] * u + beta[1] * lf;
            dt = fminf(fmaxf(dt, -0.5f), 0.5f);
            out[q0 + row] = raw_logit;
            out[Bn + q0 + row] = dt;
        }
    }
}

// ---------------- host launcher ----------------
extern "C" void kernel_launch(void* const* d_in, const int* in_sizes, int n_in,
                              void* d_out, int out_size) {
    const float* q    = (const float*)d_in[0];
    const float* R    = (const float*)d_in[1];
    const float* lnqg = (const float*)d_in[2];
    const float* lnqb = (const float*)d_in[3];
    const float* W1q  = (const float*)d_in[4];
    const float* b1q  = (const float*)d_in[5];
    const float* W2q  = (const float*)d_in[6];
    const float* b2q  = (const float*)d_in[7];
    const float* lnrg = (const float*)d_in[8];
    const float* lnrb = (const float*)d_in[9];
    const float* W1r  = (const float*)d_in[10];
    const float* b1r  = (const float*)d_in[11];
    const float* W2r  = (const float*)d_in[12];
    const float* b2r  = (const float*)d_in[13];
    const float* lndg = (const float*)d_in[14];
    const float* lndb = (const float*)d_in[15];
    const float* W1d  = (const float*)d_in[16];
    const float* b1d  = (const float*)d_in[17];
    const float* W2d  = (const float*)d_in[18];
    const float* b2d  = (const float*)d_in[19];
    const float* beta = (const float*)d_in[20];
    const float* Wlen = (const float*)d_in[21];
    const float* blen = (const float*)d_in[22];
    float* out = (float*)d_out;

    float *hb, *zq, *zr, *mu, *rs, *w1t;
    cudaGetSymbolAddress((void**)&hb, g_Hb);
    cudaGetSymbolAddress((void**)&zq, g_Zq);
    cudaGetSymbolAddress((void**)&zr, g_Zr);
    cudaGetSymbolAddress((void**)&mu, g_mu);
    cudaGetSymbolAddress((void**)&rs, g_rs);
    cudaGetSymbolAddress((void**)&w1t, g_W1T);

    cudaFuncSetAttribute(gemm1_both, cudaFuncAttributeMaxDynamicSharedMemorySize, G1_SMEM);
    cudaFuncSetAttribute(gemm2_mma, cudaFuncAttributeMaxDynamicSharedMemorySize, G2_SMEM);
    cudaFuncSetAttribute(attn_fused, cudaFuncAttributeMaxDynamicSharedMemorySize, ATTN_SMEM);

    rs_tw<<<dim3(Bn / 8, 3), 256>>>(q, R, mu, rs, W1d, w1t);
    gemm1_both<<<dim3(D2n / 128, Bn / 128, 2), 256, G1_SMEM>>>(
        q, R, W1q, W1r, lnqg, lnrg, lnqb, lnrb, b1q, b1r, mu, rs, hb);
    gemm2_mma<<<dim3(Bn / 64, 2), 256, G2_SMEM>>>(hb, W2q, W2r, b2q, b2r, zq, zr);
    attn_fused<<<Bn / 32, 256, ATTN_SMEM>>>(zq, zr, w1t, lndg, lndb, b1d, W2d, b2d,
                                            beta, Wlen, blen, out);
}